// round 17
// baseline (speedup 1.0000x reference)
#include <cuda_runtime.h>

#define BATCH 16
#define D 128
#define NN 16
#define E 120
#define OUTB (256 * 256)
#define GRID 128

// Scratch: partial P sums per 16-row d-chunk (both m from same block).
__device__ float g_Pp1[BATCH][8][256];
__device__ float g_Pp2[BATCH][8][256];
__device__ int   g_cnt_a[BATCH];   // per-batch arrive counters
__device__ int   g_cnt_b[BATCH];   // per-batch depart counters (reset)

// ---------------------------------------------------------------------------
// 128 blocks = 16 batches x 8 chunks -> one block per SM, single wave.
// Block (b, c):
//   step 1: zero-flood its 32 output rows (rows [c*32, c*32+32) of batch b)
//   Phase A: partial P1,P2 over d-chunk c for BOTH weight matrices
//   pre-spin: diagonal stores (2 rows of Mp), compacted edge-pair lists
//   per-batch barrier (8 siblings)
//   Phase B: reduce partials, sparse fixup stores for i2p in {2c, 2c+1}
// ---------------------------------------------------------------------------
__global__ void __launch_bounds__(256)
kFused(const float* __restrict__ Fs,
       const float* __restrict__ Ft,
       const float* __restrict__ Us,
       const float* __restrict__ Ut,
       const int* __restrict__ As,
       const int* __restrict__ At,
       const float* __restrict__ lam1,
       const float* __restrict__ lam2,
       float* __restrict__ out) {
    __shared__ float Fts[D * NN];     // [d'][j]
    __shared__ float ws1[16][132];    // relu(lam1+lam1^T) chunk rows
    __shared__ float ws2[16][132];    // relu(lam2+lam2^T) chunk rows
    __shared__ float Fss[16][17];     // [dloc][i]
    __shared__ float tm1[16][17];     // [dloc][j]
    __shared__ float tm2[16][17];
    __shared__ float P1s[256];
    __shared__ float P2s[256];
    __shared__ int   boths[E];
    __shared__ int   pairs1[E];       // packed (i1p<<4)|i1q, both-valid pairs
    __shared__ int   valid2[2][16];   // i2q > i2p with both[e2], per owned i2p
    __shared__ int   n1, n2[2];

    const int t  = threadIdx.x;
    const int b  = blockIdx.x >> 3;
    const int c  = blockIdx.x & 7;
    const int c0 = c * 16;

    if (t == 0) { n1 = 0; n2[0] = 0; n2[1] = 0; }

    // ========== 1. zero-flood own 32 rows immediately ==========
    {
        const float4 z = make_float4(0.f, 0.f, 0.f, 0.f);
        const int tq = t & 15;
#pragma unroll
        for (int rr = 0; rr < 2; rr++) {
            float* orow = out + b * OUTB + (c * 32 + rr * 16 + (t >> 4)) * 256;
#pragma unroll
            for (int s = 0; s < 4; s++)
                *reinterpret_cast<float4*>(orow + s * 64 + tq * 4) = z;
        }
    }

    // ========== 2. front-batched global loads ==========
    const float* ft = Ft + b * D * NN;
    const float* fs = Fs + b * D * NN;
    const float4* ft4 = reinterpret_cast<const float4*>(ft);
    const float4* l14 = reinterpret_cast<const float4*>(lam1 + c0 * D);
    const float4* l24 = reinterpret_cast<const float4*>(lam2 + c0 * D);

    const float4 rf0 = ft4[t];
    const float4 rf1 = ft4[t + 256];
    const float4 ra0 = l14[t];
    const float4 ra1 = l14[t + 256];
    const float4 rc0 = l24[t];
    const float4 rc1 = l24[t + 256];
    const float  rfs = fs[c0 * NN + t];
    float r2a[8], r2b[8];
    {
        const int d  = t & 15;
        const int dp = t >> 4;
#pragma unroll
        for (int k = 0; k < 8; k++) {
            r2a[k] = lam1[(dp + 16 * k) * D + c0 + d];
            r2b[k] = lam2[(dp + 16 * k) * D + c0 + d];
        }
    }
    int ea = 0;
    if (t < E)
        ea = (As[b * E + t] > 0) && (At[b * E + t] > 0);
    float mpv = 0.f;
    if (t < 32) {
        const int i2 = c * 2 + (t >> 4);
        const int j  = t & 15;
#pragma unroll
        for (int d = 0; d < NN; d++)
            mpv += Us[b * 256 + d * 16 + i2] * Ut[b * 256 + d * 16 + j];
    }

    // stash into smem
    *reinterpret_cast<float4*>(&Fts[4 * t])         = rf0;
    *reinterpret_cast<float4*>(&Fts[4 * (t + 256)]) = rf1;
    {
        const int e0 = 4 * t;
        const int r0 = e0 >> 7, q0 = e0 & 127;
        ws1[r0][q0]     = ra0.x;  ws1[r0][q0 + 1] = ra0.y;
        ws1[r0][q0 + 2] = ra0.z;  ws1[r0][q0 + 3] = ra0.w;
        ws2[r0][q0]     = rc0.x;  ws2[r0][q0 + 1] = rc0.y;
        ws2[r0][q0 + 2] = rc0.z;  ws2[r0][q0 + 3] = rc0.w;
        const int e1 = 4 * (t + 256);
        const int r1 = e1 >> 7, q1 = e1 & 127;
        ws1[r1][q1]     = ra1.x;  ws1[r1][q1 + 1] = ra1.y;
        ws1[r1][q1 + 2] = ra1.z;  ws1[r1][q1 + 3] = ra1.w;
        ws2[r1][q1]     = rc1.x;  ws2[r1][q1 + 1] = rc1.y;
        ws2[r1][q1 + 2] = rc1.z;  ws2[r1][q1 + 3] = rc1.w;
    }
    Fss[t >> 4][t & 15] = rfs;
    if (t < E) boths[t] = ea;
    __syncthreads();

    // pass-2 fixup: ws = relu(ws + lam^T term)
    {
        const int d  = t & 15;
        const int dp = t >> 4;
#pragma unroll
        for (int k = 0; k < 8; k++) {
            const float v1 = ws1[d][dp + 16 * k] + r2a[k];
            ws1[d][dp + 16 * k] = v1 > 0.f ? v1 : 0.f;
            const float v2 = ws2[d][dp + 16 * k] + r2b[k];
            ws2[d][dp + 16 * k] = v2 > 0.f ? v2 : 0.f;
        }
    }
    __syncthreads();

    // ========== 3. GEMM1 for both m (shared Fts operands) ==========
    {
        const int j    = t & 15;
        const int dloc = t >> 4;
        const float4* wv1 = reinterpret_cast<const float4*>(ws1[dloc]);
        const float4* wv2 = reinterpret_cast<const float4*>(ws2[dloc]);

        float a0 = 0.f, a1 = 0.f, b0 = 0.f, b1 = 0.f;
#pragma unroll
        for (int q = 0; q < D / 8; q++) {
            const float4 wa = wv1[2 * q];
            const float4 wb = wv1[2 * q + 1];
            const float4 wc = wv2[2 * q];
            const float4 wd = wv2[2 * q + 1];
            const int base = 8 * q * NN + j;
            const float f0 = Fts[base + 0 * NN];
            const float f1 = Fts[base + 1 * NN];
            const float f2 = Fts[base + 2 * NN];
            const float f3 = Fts[base + 3 * NN];
            const float f4 = Fts[base + 4 * NN];
            const float f5 = Fts[base + 5 * NN];
            const float f6 = Fts[base + 6 * NN];
            const float f7 = Fts[base + 7 * NN];
            a0 += wa.x * f0 + wa.y * f1 + wa.z * f2 + wa.w * f3;
            a1 += wb.x * f4 + wb.y * f5 + wb.z * f6 + wb.w * f7;
            b0 += wc.x * f0 + wc.y * f1 + wc.z * f2 + wc.w * f3;
            b1 += wd.x * f4 + wd.y * f5 + wd.z * f6 + wd.w * f7;
        }
        tm1[dloc][j] = a0 + a1;
        tm2[dloc][j] = b0 + b1;
    }
    __syncthreads();

    // GEMM2: partial P over this chunk, both m -> publish
    {
        const int i  = t >> 4;
        const int jj = t & 15;
        float p1 = 0.f, p2 = 0.f;
#pragma unroll
        for (int d = 0; d < 16; d++) {
            const float f = Fss[d][i];
            p1 += f * tm1[d][jj];
            p2 += f * tm2[d][jj];
        }
        g_Pp1[b][c][t] = p1;
        g_Pp2[b][c][t] = p2;
    }
    __syncthreads();

    if (t == 0) {
        __threadfence();
        atomicAdd(&g_cnt_a[b], 1);
    }

    // ========== 4. overlapped with siblings finishing ==========
    // diagonal stores for the two owned i2p rows-of-16
    if (t < 32) {
        const int p = (c * 2 + (t >> 4)) * 16 + (t & 15);
        out[b * OUTB + p * 257] = mpv;
    }

    // compacted (i1p,i1q) pair list; row k's first edge is e = k*(31-k)/2
    if (t < E && ea) {
        int r = 0;
#pragma unroll
        for (int k = 1; k < 15; k++)
            if (t >= k * (31 - k) / 2) r = k;
        const int cc = t - r * (29 - r) / 2 + 1;
        pairs1[atomicAdd(&n1, 1)] = (r << 4) | cc;
    }
    // valid i2q lists for both owned i2p
    if (t < 16) {
#pragma unroll
        for (int w = 0; w < 2; w++) {
            const int ip = c * 2 + w;
            if (t > ip) {
                const int e2 = ip * (29 - ip) / 2 + t - 1;
                if (boths[e2]) valid2[w][atomicAdd(&n2[w], 1)] = t;
            }
        }
    }

    // ========== 5. per-batch wait (8 arrivals) ==========
    if (t == 0) {
        volatile int* ca = &g_cnt_a[b];
        while (*ca < 8) __nanosleep(32);
        __threadfence();
        const int rr = atomicAdd(&g_cnt_b[b], 1);
        if (rr == 7) {
            atomicExch(&g_cnt_a[b], 0);
            atomicExch(&g_cnt_b[b], 0);
        }
    }
    __syncthreads();

    // ========== 6. reduce partials, sparse fixup stores ==========
    {
        float s1 = 0.f, s2 = 0.f;
#pragma unroll
        for (int cc = 0; cc < 8; cc++) {
            s1 += g_Pp1[b][cc][t];
            s2 += g_Pp2[b][cc][t];
        }
        P1s[t] = s1;
        P2s[t] = s2;
    }
    __syncthreads();

    {
        const int nn1 = n1;
        float* ob = out + b * OUTB;
#pragma unroll
        for (int w = 0; w < 2; w++) {
            const int i2p = c * 2 + w;
            const int nn2 = n2[w];
            for (int w2 = 0; w2 < nn2; w2++) {
                const int i2q = valid2[w][w2];
                for (int idx = t; idx < nn1; idx += 256) {
                    const int pk = pairs1[idx];
                    const int a  = pk >> 4;     // i1p
                    const int cc = pk & 15;     // i1q
                    const float val = P1s[i2p * 16 + a] + P2s[i2p * 16 + cc]
                                    + P2s[i2q * 16 + a] + P1s[i2q * 16 + cc];
                    ob[(i2p * 16 + a) * 256 + i2q * 16 + cc] = val;
                }
            }
        }
    }
}

extern "C" void kernel_launch(void* const* d_in, const int* in_sizes, int n_in,
                              void* d_out, int out_size) {
    const int*   As   = (const int*)d_in[0];
    const int*   At   = (const int*)d_in[1];
    const float* Fs   = (const float*)d_in[2];
    const float* Ft   = (const float*)d_in[3];
    const float* Us   = (const float*)d_in[4];
    const float* Ut   = (const float*)d_in[5];
    const float* lam1 = (const float*)d_in[6];
    const float* lam2 = (const float*)d_in[7];
    float* out = (float*)d_out;

    kFused<<<GRID, 256>>>(Fs, Ft, Us, Ut, As, At, lam1, lam2, out);
}